// round 12
// baseline (speedup 1.0000x reference)
#include <cuda_runtime.h>
#include <cuda_fp16.h>
#include <math.h>
#include <stdint.h>

#define DDIM   512
#define MTOK   32768
#define NCODE  8192
#define MT     128
#define NTILE  128
#define NSTG   3
#define MARGIN_INT 2048       // int screen margin = 8.0 real units * 256
#define CAP    192
#define CTA_THR 128
#define NTHREADS_TOT 32768
#define SURV_MAX (1 << 20)
#define RBEST_INIT 0x7F000000 // large but overflow-safe vs +MARGIN_INT

#define A_BYTES (MT*128)            // 16KB (128 rows x 128B int8 K-chunk)
#define B_BYTES (NTILE*128)         // 16KB
#define STG_BYTES (A_BYTES + B_BYTES)
#define DYN_SMEM (NSTG * STG_BYTES) // 96KB

#define SWZ(o) ((o) ^ ((((o) >> 3) & 0x70)))

// ---------------- device scratch ----------------
__device__ char  g_zq[(size_t)MTOK * DDIM];
__device__ char  g_eq[(size_t)NCODE * DDIM];
__device__ float g_enorm[NCODE];
__device__ int   g_eint[NCODE];
__device__ int   g_counts[NCODE];
__device__ float g_tokloss[MTOK];
__device__ unsigned long long g_key[MTOK];
__device__ unsigned long long g_ent[(size_t)NTHREADS_TOT * CAP];
__device__ int   g_cnt[NTHREADS_TOT];
__device__ unsigned int  g_bestbits[MTOK];
__device__ unsigned char g_overflow[MTOK];
__device__ int   g_surv[SURV_MAX];
__device__ int   g_nsurv;

// ---------------- helpers ----------------
__device__ __forceinline__ uint32_t smem_u32(const void* p) {
    return (uint32_t)__cvta_generic_to_shared(p);
}
__device__ __forceinline__ void cpasync16(uint32_t dst, const void* src) {
    asm volatile("cp.async.cg.shared.global [%0], [%1], 16;" :: "r"(dst), "l"(src) : "memory");
}
__device__ __forceinline__ void cp_commit() {
    asm volatile("cp.async.commit_group;" ::: "memory");
}
template<int N> __device__ __forceinline__ void cp_wait() {
    asm volatile("cp.async.wait_group %0;" :: "n"(N) : "memory");
}
__device__ __forceinline__ void ldsm4(uint32_t& r0, uint32_t& r1, uint32_t& r2, uint32_t& r3,
                                      uint32_t a) {
    asm volatile("ldmatrix.sync.aligned.m8n8.x4.shared.b16 {%0,%1,%2,%3}, [%4];"
                 : "=r"(r0), "=r"(r1), "=r"(r2), "=r"(r3) : "r"(a));
}
__device__ __forceinline__ void mma_s8(int* c, const uint32_t* a, const uint32_t* b) {
    asm volatile(
        "mma.sync.aligned.m16n8k32.row.col.s32.s8.s8.s32 "
        "{%0,%1,%2,%3}, {%4,%5,%6,%7}, {%8,%9}, {%0,%1,%2,%3};"
        : "+r"(c[0]), "+r"(c[1]), "+r"(c[2]), "+r"(c[3])
        : "r"(a[0]), "r"(a[1]), "r"(a[2]), "r"(a[3]), "r"(b[0]), "r"(b[1]));
}
__device__ __forceinline__ unsigned orderbits(float v) {
    unsigned u = __float_as_uint(v);
    return (u & 0x80000000u) ? ~u : (u | 0x80000000u);
}
__device__ __forceinline__ unsigned long long packkey(float d, int c) {
    return ((unsigned long long)orderbits(d) << 32) | (unsigned)c;
}
__device__ __forceinline__ char q8(float v) {
    int q = __float2int_rn(16.f * v);
    q = q > 127 ? 127 : (q < -127 ? -127 : q);
    return (char)q;
}

// ---------------- setup ----------------
__global__ void init_kernel() {
    int i = blockIdx.x * blockDim.x + threadIdx.x;
    if (i < NCODE) g_counts[i] = 0;
    if (i < MTOK) {
        g_key[i] = 0xFFFFFFFFFFFFFFFFull;
        g_bestbits[i] = 0xFFFFFFFFu;
        g_overflow[i] = 0;
    }
    if (i == 0) g_nsurv = 0;
}

__global__ void convert_kernel(const float* __restrict__ x, char* __restrict__ out, int n4) {
    int i = blockIdx.x * blockDim.x + threadIdx.x;
    if (i >= n4) return;
    float4 v = ((const float4*)x)[i];
    uchar4 p;
    p.x = (unsigned char)q8(v.x); p.y = (unsigned char)q8(v.y);
    p.z = (unsigned char)q8(v.z); p.w = (unsigned char)q8(v.w);
    ((uchar4*)out)[i] = p;
}

// quantize embedding + fp32 norm + int norm
__global__ void convert_enorm_kernel(const float* __restrict__ emb, char* __restrict__ out) {
    int c = blockIdx.x, tid = threadIdx.x;   // 128 threads
    float4 v = ((const float4*)(emb + (size_t)c * DDIM))[tid];
    int qx = (int)(signed char)q8(v.x), qy = (int)(signed char)q8(v.y);
    int qz = (int)(signed char)q8(v.z), qw = (int)(signed char)q8(v.w);
    uchar4 p;
    p.x = (unsigned char)(char)qx; p.y = (unsigned char)(char)qy;
    p.z = (unsigned char)(char)qz; p.w = (unsigned char)(char)qw;
    ((uchar4*)(out + (size_t)c * DDIM))[tid] = p;
    float s = v.x * v.x + v.y * v.y + v.z * v.z + v.w * v.w;
    int si = qx * qx + qy * qy + qz * qz + qw * qw;
    #pragma unroll
    for (int o = 16; o > 0; o >>= 1) {
        s  += __shfl_down_sync(0xffffffffu, s, o);
        si += __shfl_down_sync(0xffffffffu, si, o);
    }
    __shared__ float ws[4];
    __shared__ int   wi[4];
    if ((tid & 31) == 0) { ws[tid >> 5] = s; wi[tid >> 5] = si; }
    __syncthreads();
    if (tid == 0) {
        g_enorm[c] = ws[0] + ws[1] + ws[2] + ws[3];
        g_eint[c]  = wi[0] + wi[1] + wi[2] + wi[3];
    }
}

// ---------------- fused int8 MMA GEMM + candidate emission ----------------
// CTA: 128 threads, 4 warps in 2(M) x 2(N); warp tile 64x64; 2 CTAs/SM.
__global__ void __launch_bounds__(CTA_THR, 2) hmma_argmin_kernel(int C) {
    extern __shared__ __align__(1024) char dyn[];
    const uint32_t sb = smem_u32(dyn);
    const int tid = threadIdx.x;
    const int wid = tid >> 5, l = tid & 31;
    const int wm = wid >> 1, wn = wid & 1;
    const int m0 = blockIdx.x * MT;
    const int nct = C / NTILE;          // 64
    const int TOT = nct * 4;            // 256

    const char* Z = g_zq;
    const char* E = g_eq;

    int rbest[8];
    #pragma unroll
    for (int r = 0; r < 8; r++) rbest[r] = RBEST_INIT;
    uint32_t mmeta[8];
    #pragma unroll
    for (int r = 0; r < 8; r++) {
        int am = r >> 1, h = r & 1;
        int row = wm * 64 + am * 16 + h * 8 + (l >> 2);
        mmeta[r] = (uint32_t)(m0 + row) << 13;
    }
    int cnt = 0;
    unsigned long long* ent = g_ent + (size_t)(blockIdx.x * CTA_THR + tid) * CAP;

    auto load_chunk = [&](int i) {
        int t = i >> 2, ch = i & 3;
        int kk0 = ch * 128;
        int c0 = t * NTILE;
        uint32_t abase = sb + (i % NSTG) * STG_BYTES;
        uint32_t bbase = abase + A_BYTES;
        #pragma unroll
        for (int q = 0; q < 8; q++) {
            int f = tid + q * CTA_THR;
            int row = f >> 3, kq = (f & 7) * 16;
            cpasync16(abase + SWZ(row * 128 + kq),
                      Z + ((size_t)(m0 + row) * DDIM + kk0 + kq));
            cpasync16(bbase + SWZ(row * 128 + kq),
                      E + ((size_t)(c0 + row) * DDIM + kk0 + kq));
        }
        cp_commit();
    };

    load_chunk(0);
    load_chunk(1);

    int acc[4][8][4];
    #pragma unroll
    for (int am = 0; am < 4; am++)
        #pragma unroll
        for (int bn = 0; bn < 8; bn++)
            #pragma unroll
            for (int k = 0; k < 4; k++) acc[am][bn][k] = 0;

    const int arow = wm * 64 + (l & 7) + ((l >> 3) & 1) * 8;     // + am*16
    const int acol = (l >> 4) * 16;
    const uint32_t axor = (uint32_t)((arow & 7) << 4);
    const uint32_t aoff0 = (uint32_t)(arow * 128);
    const int brow = wn * 64 + (l & 7) + (l >> 4) * 8;           // + bp*16
    const int bcol = ((l >> 3) & 1) * 16;
    const uint32_t bxor = (uint32_t)((brow & 7) << 4);
    const uint32_t boff0 = (uint32_t)(brow * 128);

    for (int i = 0; i < TOT; i++) {
        if (i + 1 < TOT) cp_wait<1>(); else cp_wait<0>();
        __syncthreads();
        if (i + 2 < TOT) load_chunk(i + 2);

        uint32_t abase = sb + (i % NSTG) * STG_BYTES;
        uint32_t bbase = abase + A_BYTES;

        #pragma unroll
        for (int kk = 0; kk < 4; kk++) {
            const uint32_t akb = ((uint32_t)(kk * 32 + acol)) ^ axor;
            const uint32_t bkb = ((uint32_t)(kk * 32 + bcol)) ^ bxor;
            uint32_t af[4][4];
            #pragma unroll
            for (int am = 0; am < 4; am++)
                ldsm4(af[am][0], af[am][1], af[am][2], af[am][3],
                      abase + aoff0 + (uint32_t)(am * 2048) + akb);
            uint32_t bcur[4], bnxt[4];
            ldsm4(bcur[0], bcur[1], bcur[2], bcur[3], bbase + boff0 + bkb);
            #pragma unroll
            for (int bp = 0; bp < 4; bp++) {
                if (bp < 3)
                    ldsm4(bnxt[0], bnxt[1], bnxt[2], bnxt[3],
                          bbase + boff0 + (uint32_t)((bp + 1) * 2048) + bkb);
                #pragma unroll
                for (int am = 0; am < 4; am++) {
                    mma_s8(acc[am][2 * bp],     af[am], bcur);
                    mma_s8(acc[am][2 * bp + 1], af[am], bcur + 2);
                }
                #pragma unroll
                for (int q = 0; q < 4; q++) bcur[q] = bnxt[q];
            }
        }

        if ((i & 3) == 3) {
            int c0 = (i >> 2) * NTILE;
            #pragma unroll
            for (int bn = 0; bn < 8; bn++) {
                #pragma unroll
                for (int j = 0; j < 2; j++) {
                    int c = c0 + wn * 64 + bn * 8 + (l & 3) * 2 + j;
                    int e = __ldg(&g_eint[c]);
                    #pragma unroll
                    for (int am = 0; am < 4; am++) {
                        #pragma unroll
                        for (int h = 0; h < 2; h++) {
                            int r = am * 2 + h;
                            int v = e - 2 * acc[am][bn][h * 2 + j];
                            if (v < rbest[r] + MARGIN_INT) {   // rbest <= RBEST_INIT: no overflow
                                int pos = cnt < CAP ? cnt : CAP - 1;
                                ent[pos] = ((unsigned long long)(mmeta[r] | (uint32_t)c) << 32)
                                         | ((unsigned)v ^ 0x80000000u);
                                cnt++;
                            }
                            rbest[r] = v < rbest[r] ? v : rbest[r];
                        }
                    }
                }
            }
            #pragma unroll
            for (int am = 0; am < 4; am++)
                #pragma unroll
                for (int bn = 0; bn < 8; bn++)
                    #pragma unroll
                    for (int k = 0; k < 4; k++) acc[am][bn][k] = 0;
        }
    }

    g_cnt[blockIdx.x * CTA_THR + tid] = cnt;
}

// ---------------- filter A: per-token quantized best via atomicMin ----------------
__global__ void filter_a_kernel() {
    int gid = blockIdx.x * blockDim.x + threadIdx.x;   // 0..32767
    int cnt = g_cnt[gid];
    if (cnt > CAP) {
        int cta = gid >> 7, tid = gid & 127;
        int wid = tid >> 5, l = tid & 31;
        int wm = wid >> 1;
        #pragma unroll
        for (int r = 0; r < 8; r++) {
            int am = r >> 1, h = r & 1;
            int m = cta * MT + wm * 64 + am * 16 + h * 8 + (l >> 2);
            g_overflow[m] = 1;
        }
        cnt = CAP;
    }
    const unsigned long long* ent = g_ent + (size_t)gid * CAP;
    for (int i = 0; i < cnt; i++) {
        unsigned long long e = ent[i];
        unsigned meta = (unsigned)(e >> 32);
        unsigned ov = (unsigned)e;
        int m = meta >> 13;
        atomicMin(&g_bestbits[m], ov);
    }
}

// ---------------- filter B: compact survivors ----------------
__global__ void filter_b_kernel() {
    int gid = blockIdx.x * blockDim.x + threadIdx.x;
    int cnt = g_cnt[gid];
    if (cnt > CAP) cnt = CAP;
    const unsigned long long* ent = g_ent + (size_t)gid * CAP;
    for (int i = 0; i < cnt; i++) {
        unsigned long long e = ent[i];
        unsigned meta = (unsigned)(e >> 32);
        int v = (int)((unsigned)e ^ 0x80000000u);
        int m = meta >> 13;
        int best = (int)(g_bestbits[m] ^ 0x80000000u);
        if (v < best + MARGIN_INT) {
            int pos = atomicAdd(&g_nsurv, 1);
            if (pos < SURV_MAX) g_surv[pos] = (int)meta;
            else g_overflow[m] = 1;
        }
    }
}

// ---------------- exact fp32 scoring of survivors ----------------
__global__ void __launch_bounds__(256) exact_kernel(const float* __restrict__ z,
                                                    const float* __restrict__ emb) {
    int n = g_nsurv;
    if (n > SURV_MAX) n = SURV_MAX;
    int gw = blockIdx.x * 8 + (threadIdx.x >> 5);
    int l = threadIdx.x & 31;
    const int NW = gridDim.x * 8;
    for (int i = gw; i < n; i += NW) {
        unsigned meta = (unsigned)g_surv[i];
        int m = meta >> 13, c = meta & 0x1FFF;
        const float4* zr = (const float4*)(z + (size_t)m * DDIM);
        const float4* er = (const float4*)(emb + (size_t)c * DDIM);
        float a0 = 0.f, a1 = 0.f;
        #pragma unroll
        for (int q = 0; q < 4; q++) {
            float4 zv = __ldg(zr + q * 32 + l);
            float4 ev = __ldg(er + q * 32 + l);
            a0 = fmaf(zv.x, ev.x, a0);
            a1 = fmaf(zv.y, ev.y, a1);
            a0 = fmaf(zv.z, ev.z, a0);
            a1 = fmaf(zv.w, ev.w, a1);
        }
        float s = a0 + a1;
        #pragma unroll
        for (int o = 16; o > 0; o >>= 1) s += __shfl_down_sync(0xffffffffu, s, o);
        if (l == 0) {
            float v = fmaf(-2.f, s, __ldg(&g_enorm[c]));
            atomicMin(&g_key[m], packkey(v, c));
        }
    }
}

// ---------------- fallback: full exact scan for overflowed tokens ----------------
__global__ void __launch_bounds__(256) fallback_kernel(const float* __restrict__ z,
                                                       const float* __restrict__ emb) {
    for (int m = blockIdx.x; m < MTOK; m += gridDim.x) {
        if (!g_overflow[m]) continue;
        int tid = threadIdx.x;
        for (int c = tid; c < NCODE; c += 256) {
            const float* zr = z + (size_t)m * DDIM;
            const float* er = emb + (size_t)c * DDIM;
            float a = 0.f;
            for (int k = 0; k < DDIM; k++) a = fmaf(__ldg(zr + k), __ldg(er + k), a);
            float v = fmaf(-2.f, a, __ldg(&g_enorm[c]));
            atomicMin(&g_key[m], packkey(v, c));
        }
    }
}

// ---------------- gather / stats ----------------
__global__ void gather_kernel(const float* __restrict__ z, const float* __restrict__ emb,
                              float* __restrict__ out, float* __restrict__ outCodes,
                              int writeCodes) {
    int m = blockIdx.x, tid = threadIdx.x;
    int c = (int)(g_key[m] & 0x1FFFull);
    float4 zv = ((const float4*)(z + (size_t)m * DDIM))[tid];
    float4 ev = ((const float4*)(emb + (size_t)c * DDIM))[tid];
    float4 d, s, t;
    d.x = ev.x - zv.x; d.y = ev.y - zv.y; d.z = ev.z - zv.z; d.w = ev.w - zv.w;
    s.x = zv.x + d.x;  s.y = zv.y + d.y;  s.z = zv.z + d.z;  s.w = zv.w + d.w;
    ((float4*)(out + (size_t)m * DDIM))[tid] = s;
    t.x = s.x - zv.x; t.y = s.y - zv.y; t.z = s.z - zv.z; t.w = s.w - zv.w;
    float ls = t.x * t.x + t.y * t.y + t.z * t.z + t.w * t.w;
    #pragma unroll
    for (int o = 16; o > 0; o >>= 1) ls += __shfl_down_sync(0xffffffffu, ls, o);
    __shared__ float ws[4];
    if ((tid & 31) == 0) ws[tid >> 5] = ls;
    __syncthreads();
    if (tid == 0) {
        g_tokloss[m] = ws[0] + ws[1] + ws[2] + ws[3];
        atomicAdd(&g_counts[c], 1);
        if (writeCodes) outCodes[m] = (float)c;
    }
}

__global__ void finalize_kernel(float* __restrict__ outStats, int M, int C, int hasStats) {
    __shared__ float sh[1024];
    int tid = threadIdx.x;
    float s = 0.f;
    for (int i = tid; i < M; i += 1024) s += g_tokloss[i];
    sh[tid] = s; __syncthreads();
    for (int o = 512; o > 0; o >>= 1) { if (tid < o) sh[tid] += sh[tid + o]; __syncthreads(); }
    float loss = 0.25f * sh[0] / ((float)M * (float)DDIM);
    __syncthreads();
    float p = 0.f;
    float invM = 1.f / (float)M;
    for (int i = tid; i < C; i += 1024) {
        float pr = (float)g_counts[i] * invM;
        p += pr * logf(pr + 1e-10f);
    }
    sh[tid] = p; __syncthreads();
    for (int o = 512; o > 0; o >>= 1) { if (tid < o) sh[tid] += sh[tid + o]; __syncthreads(); }
    if (tid == 0 && hasStats) {
        outStats[0] = loss;
        outStats[1] = expf(-sh[0]);
    }
}

extern "C" void kernel_launch(void* const* d_in, const int* in_sizes, int n_in,
                              void* d_out, int out_size) {
    const float* z   = (const float*)d_in[0];
    const float* emb = (const float*)d_in[1];
    float* out = (float*)d_out;

    int M = in_sizes[0] / DDIM;   // 32768
    int C = in_sizes[1] / DDIM;   // 8192

    static int attr_done = 0;
    if (!attr_done) {
        cudaFuncSetAttribute(hmma_argmin_kernel, cudaFuncAttributeMaxDynamicSharedMemorySize, DYN_SMEM);
        attr_done = 1;
    }

    char* zq; cudaGetSymbolAddress((void**)&zq, g_zq);
    char* eq; cudaGetSymbolAddress((void**)&eq, g_eq);

    init_kernel<<<(MTOK + 255) / 256, 256>>>();                       // 1
    convert_kernel<<<(M * DDIM / 4 + 255) / 256, 256>>>(z, zq, M * DDIM / 4);  // 2
    convert_enorm_kernel<<<C, 128>>>(emb, eq);                        // 3
    hmma_argmin_kernel<<<M / MT, CTA_THR, DYN_SMEM>>>(C);             // 4  <-- profiled slot
    filter_a_kernel<<<NTHREADS_TOT / 256, 256>>>();                   // 5
    filter_b_kernel<<<NTHREADS_TOT / 256, 256>>>();                   // 6
    exact_kernel<<<1024, 256>>>(z, emb);                              // 7
    fallback_kernel<<<256, 256>>>(z, emb);                            // 8
    long long zqN = (long long)M * DDIM;
    int writeCodes = (out_size >= zqN + M) ? 1 : 0;
    gather_kernel<<<M, 128>>>(z, emb, out, out + zqN, writeCodes);    // 9
    int hasStats = (out_size >= zqN + M + 2) ? 1 : 0;
    finalize_kernel<<<1, 1024>>>(out + zqN + M, M, C, hasStats);      // 10
}

// round 13
// speedup vs baseline: 1.0032x; 1.0032x over previous
#include <cuda_runtime.h>
#include <cuda_fp16.h>
#include <math.h>
#include <stdint.h>

#define DDIM   512
#define MTOK   32768
#define NCODE  8192
#define MT     128
#define NTILE  128
#define NSTG   3
#define MARGIN_INT 3072       // 12.0 real units * 256 (6 sigma of screen err-diff)
#define CAP    384
#define CTA_THR 128
#define NTHREADS_TOT 32768
#define SURV_MAX (1 << 20)
#define RBEST_INIT 0x7F000000

#define A_BYTES (MT*128)
#define B_BYTES (NTILE*128)
#define STG_BYTES (A_BYTES + B_BYTES)
#define DYN_SMEM (NSTG * STG_BYTES)   // 96KB

#define SWZ(o) ((o) ^ ((((o) >> 3) & 0x70)))

// ---------------- device scratch ----------------
__device__ char  g_zq[(size_t)MTOK * DDIM];
__device__ char  g_eq[(size_t)NCODE * DDIM];
__device__ float g_enorm[NCODE];
__device__ int   g_eint[NCODE];
__device__ int   g_counts[NCODE];
__device__ float g_tokloss[MTOK];
__device__ unsigned long long g_key[MTOK];
__device__ unsigned long long g_ent[(size_t)NTHREADS_TOT * CAP];   // 100 MB
__device__ int   g_cnt[NTHREADS_TOT];
__device__ unsigned int  g_bestbits[MTOK];
__device__ unsigned char g_overflow[MTOK];
__device__ int   g_surv[SURV_MAX];
__device__ int   g_nsurv;

// ---------------- helpers ----------------
__device__ __forceinline__ uint32_t smem_u32(const void* p) {
    return (uint32_t)__cvta_generic_to_shared(p);
}
__device__ __forceinline__ void cpasync16(uint32_t dst, const void* src) {
    asm volatile("cp.async.cg.shared.global [%0], [%1], 16;" :: "r"(dst), "l"(src) : "memory");
}
__device__ __forceinline__ void cp_commit() {
    asm volatile("cp.async.commit_group;" ::: "memory");
}
template<int N> __device__ __forceinline__ void cp_wait() {
    asm volatile("cp.async.wait_group %0;" :: "n"(N) : "memory");
}
__device__ __forceinline__ void ldsm4(uint32_t& r0, uint32_t& r1, uint32_t& r2, uint32_t& r3,
                                      uint32_t a) {
    asm volatile("ldmatrix.sync.aligned.m8n8.x4.shared.b16 {%0,%1,%2,%3}, [%4];"
                 : "=r"(r0), "=r"(r1), "=r"(r2), "=r"(r3) : "r"(a));
}
__device__ __forceinline__ void mma_s8(int* c, const uint32_t* a, const uint32_t* b) {
    asm volatile(
        "mma.sync.aligned.m16n8k32.row.col.s32.s8.s8.s32 "
        "{%0,%1,%2,%3}, {%4,%5,%6,%7}, {%8,%9}, {%0,%1,%2,%3};"
        : "+r"(c[0]), "+r"(c[1]), "+r"(c[2]), "+r"(c[3])
        : "r"(a[0]), "r"(a[1]), "r"(a[2]), "r"(a[3]), "r"(b[0]), "r"(b[1]));
}
__device__ __forceinline__ unsigned orderbits(float v) {
    unsigned u = __float_as_uint(v);
    return (u & 0x80000000u) ? ~u : (u | 0x80000000u);
}
__device__ __forceinline__ unsigned long long packkey(float d, int c) {
    return ((unsigned long long)orderbits(d) << 32) | (unsigned)c;
}
__device__ __forceinline__ char q8(float v) {
    int q = __float2int_rn(16.f * v);
    q = q > 127 ? 127 : (q < -127 ? -127 : q);
    return (char)q;
}

// ---------------- setup ----------------
__global__ void init_kernel() {
    int i = blockIdx.x * blockDim.x + threadIdx.x;
    if (i < NCODE) g_counts[i] = 0;
    if (i < MTOK) {
        g_key[i] = 0xFFFFFFFFFFFFFFFFull;
        g_bestbits[i] = 0xFFFFFFFFu;
        g_overflow[i] = 0;
    }
    if (i == 0) g_nsurv = 0;
}

__global__ void convert_kernel(const float* __restrict__ x, char* __restrict__ out, int n4) {
    int i = blockIdx.x * blockDim.x + threadIdx.x;
    if (i >= n4) return;
    float4 v = ((const float4*)x)[i];
    uchar4 p;
    p.x = (unsigned char)q8(v.x); p.y = (unsigned char)q8(v.y);
    p.z = (unsigned char)q8(v.z); p.w = (unsigned char)q8(v.w);
    ((uchar4*)out)[i] = p;
}

__global__ void convert_enorm_kernel(const float* __restrict__ emb, char* __restrict__ out) {
    int c = blockIdx.x, tid = threadIdx.x;
    float4 v = ((const float4*)(emb + (size_t)c * DDIM))[tid];
    int qx = (int)(signed char)q8(v.x), qy = (int)(signed char)q8(v.y);
    int qz = (int)(signed char)q8(v.z), qw = (int)(signed char)q8(v.w);
    uchar4 p;
    p.x = (unsigned char)(char)qx; p.y = (unsigned char)(char)qy;
    p.z = (unsigned char)(char)qz; p.w = (unsigned char)(char)qw;
    ((uchar4*)(out + (size_t)c * DDIM))[tid] = p;
    float s = v.x * v.x + v.y * v.y + v.z * v.z + v.w * v.w;
    int si = qx * qx + qy * qy + qz * qz + qw * qw;
    #pragma unroll
    for (int o = 16; o > 0; o >>= 1) {
        s  += __shfl_down_sync(0xffffffffu, s, o);
        si += __shfl_down_sync(0xffffffffu, si, o);
    }
    __shared__ float ws[4];
    __shared__ int   wi[4];
    if ((tid & 31) == 0) { ws[tid >> 5] = s; wi[tid >> 5] = si; }
    __syncthreads();
    if (tid == 0) {
        g_enorm[c] = ws[0] + ws[1] + ws[2] + ws[3];
        g_eint[c]  = wi[0] + wi[1] + wi[2] + wi[3];
    }
}

// ---------------- fused int8 MMA GEMM + candidate emission ----------------
__global__ void __launch_bounds__(CTA_THR, 2) hmma_argmin_kernel(int C) {
    extern __shared__ __align__(1024) char dyn[];
    const uint32_t sb = smem_u32(dyn);
    const int tid = threadIdx.x;
    const int wid = tid >> 5, l = tid & 31;
    const int wm = wid >> 1, wn = wid & 1;
    const int m0 = blockIdx.x * MT;
    const int nct = C / NTILE;
    const int TOT = nct * 4;

    const char* Z = g_zq;
    const char* E = g_eq;

    int rbest[8];
    #pragma unroll
    for (int r = 0; r < 8; r++) rbest[r] = RBEST_INIT;
    uint32_t mmeta[8];
    #pragma unroll
    for (int r = 0; r < 8; r++) {
        int am = r >> 1, h = r & 1;
        int row = wm * 64 + am * 16 + h * 8 + (l >> 2);
        mmeta[r] = (uint32_t)(m0 + row) << 13;
    }
    int cnt = 0;
    unsigned long long* ent = g_ent + (size_t)(blockIdx.x * CTA_THR + tid) * CAP;

    auto load_chunk = [&](int i) {
        int t = i >> 2, ch = i & 3;
        int kk0 = ch * 128;
        int c0 = t * NTILE;
        uint32_t abase = sb + (i % NSTG) * STG_BYTES;
        uint32_t bbase = abase + A_BYTES;
        #pragma unroll
        for (int q = 0; q < 8; q++) {
            int f = tid + q * CTA_THR;
            int row = f >> 3, kq = (f & 7) * 16;
            cpasync16(abase + SWZ(row * 128 + kq),
                      Z + ((size_t)(m0 + row) * DDIM + kk0 + kq));
            cpasync16(bbase + SWZ(row * 128 + kq),
                      E + ((size_t)(c0 + row) * DDIM + kk0 + kq));
        }
        cp_commit();
    };

    load_chunk(0);
    load_chunk(1);

    int acc[4][8][4];
    #pragma unroll
    for (int am = 0; am < 4; am++)
        #pragma unroll
        for (int bn = 0; bn < 8; bn++)
            #pragma unroll
            for (int k = 0; k < 4; k++) acc[am][bn][k] = 0;

    const int arow = wm * 64 + (l & 7) + ((l >> 3) & 1) * 8;
    const int acol = (l >> 4) * 16;
    const uint32_t axor = (uint32_t)((arow & 7) << 4);
    const uint32_t aoff0 = (uint32_t)(arow * 128);
    const int brow = wn * 64 + (l & 7) + (l >> 4) * 8;
    const int bcol = ((l >> 3) & 1) * 16;
    const uint32_t bxor = (uint32_t)((brow & 7) << 4);
    const uint32_t boff0 = (uint32_t)(brow * 128);

    for (int i = 0; i < TOT; i++) {
        if (i + 1 < TOT) cp_wait<1>(); else cp_wait<0>();
        __syncthreads();
        if (i + 2 < TOT) load_chunk(i + 2);

        uint32_t abase = sb + (i % NSTG) * STG_BYTES;
        uint32_t bbase = abase + A_BYTES;

        #pragma unroll
        for (int kk = 0; kk < 4; kk++) {
            const uint32_t akb = ((uint32_t)(kk * 32 + acol)) ^ axor;
            const uint32_t bkb = ((uint32_t)(kk * 32 + bcol)) ^ bxor;
            uint32_t af[4][4];
            #pragma unroll
            for (int am = 0; am < 4; am++)
                ldsm4(af[am][0], af[am][1], af[am][2], af[am][3],
                      abase + aoff0 + (uint32_t)(am * 2048) + akb);
            uint32_t bcur[4], bnxt[4];
            ldsm4(bcur[0], bcur[1], bcur[2], bcur[3], bbase + boff0 + bkb);
            #pragma unroll
            for (int bp = 0; bp < 4; bp++) {
                if (bp < 3)
                    ldsm4(bnxt[0], bnxt[1], bnxt[2], bnxt[3],
                          bbase + boff0 + (uint32_t)((bp + 1) * 2048) + bkb);
                #pragma unroll
                for (int am = 0; am < 4; am++) {
                    mma_s8(acc[am][2 * bp],     af[am], bcur);
                    mma_s8(acc[am][2 * bp + 1], af[am], bcur + 2);
                }
                #pragma unroll
                for (int q = 0; q < 4; q++) bcur[q] = bnxt[q];
            }
        }

        if ((i & 3) == 3) {
            int c0 = (i >> 2) * NTILE;
            #pragma unroll
            for (int bn = 0; bn < 8; bn++) {
                #pragma unroll
                for (int j = 0; j < 2; j++) {
                    int c = c0 + wn * 64 + bn * 8 + (l & 3) * 2 + j;
                    int e = __ldg(&g_eint[c]);
                    #pragma unroll
                    for (int am = 0; am < 4; am++) {
                        #pragma unroll
                        for (int h = 0; h < 2; h++) {
                            int r = am * 2 + h;
                            int v = e - 2 * acc[am][bn][h * 2 + j];
                            if (v < rbest[r] + MARGIN_INT) {
                                int pos = cnt < CAP ? cnt : CAP - 1;
                                ent[pos] = ((unsigned long long)(mmeta[r] | (uint32_t)c) << 32)
                                         | ((unsigned)v ^ 0x80000000u);
                                cnt++;
                            }
                            rbest[r] = v < rbest[r] ? v : rbest[r];
                        }
                    }
                }
            }
            #pragma unroll
            for (int am = 0; am < 4; am++)
                #pragma unroll
                for (int bn = 0; bn < 8; bn++)
                    #pragma unroll
                    for (int k = 0; k < 4; k++) acc[am][bn][k] = 0;
        }
    }

    g_cnt[blockIdx.x * CTA_THR + tid] = cnt;
    // fused filter A: publish per-slot screen best; mark overflow inline
    #pragma unroll
    for (int r = 0; r < 8; r++) {
        int m = (int)(mmeta[r] >> 13);
        atomicMin(&g_bestbits[m], (unsigned)rbest[r] ^ 0x80000000u);
        if (cnt > CAP) g_overflow[m] = 1;
    }
}

// ---------------- filter B: compact survivors vs global screen best ----------------
__global__ void filter_b_kernel() {
    int gid = blockIdx.x * blockDim.x + threadIdx.x;
    int cnt = g_cnt[gid];
    if (cnt > CAP) cnt = CAP;
    const unsigned long long* ent = g_ent + (size_t)gid * CAP;
    for (int i = 0; i < cnt; i++) {
        unsigned long long e = ent[i];
        unsigned meta = (unsigned)(e >> 32);
        int v = (int)((unsigned)e ^ 0x80000000u);
        int m = meta >> 13;
        int best = (int)(g_bestbits[m] ^ 0x80000000u);
        if (v < best + MARGIN_INT) {
            int pos = atomicAdd(&g_nsurv, 1);
            if (pos < SURV_MAX) g_surv[pos] = (int)meta;
            else g_overflow[m] = 1;
        }
    }
}

// ---------------- exact fp32 scoring of survivors ----------------
__global__ void __launch_bounds__(256) exact_kernel(const float* __restrict__ z,
                                                    const float* __restrict__ emb) {
    int n = g_nsurv;
    if (n > SURV_MAX) n = SURV_MAX;
    int gw = blockIdx.x * 8 + (threadIdx.x >> 5);
    int l = threadIdx.x & 31;
    const int NW = gridDim.x * 8;
    for (int i = gw; i < n; i += NW) {
        unsigned meta = (unsigned)g_surv[i];
        int m = meta >> 13, c = meta & 0x1FFF;
        const float4* zr = (const float4*)(z + (size_t)m * DDIM);
        const float4* er = (const float4*)(emb + (size_t)c * DDIM);
        float a0 = 0.f, a1 = 0.f;
        #pragma unroll
        for (int q = 0; q < 4; q++) {
            float4 zv = __ldg(zr + q * 32 + l);
            float4 ev = __ldg(er + q * 32 + l);
            a0 = fmaf(zv.x, ev.x, a0);
            a1 = fmaf(zv.y, ev.y, a1);
            a0 = fmaf(zv.z, ev.z, a0);
            a1 = fmaf(zv.w, ev.w, a1);
        }
        float s = a0 + a1;
        #pragma unroll
        for (int o = 16; o > 0; o >>= 1) s += __shfl_down_sync(0xffffffffu, s, o);
        if (l == 0) {
            float v = fmaf(-2.f, s, __ldg(&g_enorm[c]));
            atomicMin(&g_key[m], packkey(v, c));
        }
    }
}

// ---------------- fallback: full exact scan for overflowed tokens (expected none) ----------------
__global__ void __launch_bounds__(256) fallback_kernel(const float* __restrict__ z,
                                                       const float* __restrict__ emb) {
    for (int m = blockIdx.x; m < MTOK; m += gridDim.x) {
        if (!g_overflow[m]) continue;
        int tid = threadIdx.x;
        for (int c = tid; c < NCODE; c += 256) {
            const float* zr = z + (size_t)m * DDIM;
            const float* er = emb + (size_t)c * DDIM;
            float a = 0.f;
            for (int k = 0; k < DDIM; k++) a = fmaf(__ldg(zr + k), __ldg(er + k), a);
            float v = fmaf(-2.f, a, __ldg(&g_enorm[c]));
            atomicMin(&g_key[m], packkey(v, c));
        }
    }
}

// ---------------- gather / stats ----------------
__global__ void gather_kernel(const float* __restrict__ z, const float* __restrict__ emb,
                              float* __restrict__ out, float* __restrict__ outCodes,
                              int writeCodes) {
    int m = blockIdx.x, tid = threadIdx.x;
    int c = (int)(g_key[m] & 0x1FFFull);
    float4 zv = ((const float4*)(z + (size_t)m * DDIM))[tid];
    float4 ev = ((const float4*)(emb + (size_t)c * DDIM))[tid];
    float4 d, s, t;
    d.x = ev.x - zv.x; d.y = ev.y - zv.y; d.z = ev.z - zv.z; d.w = ev.w - zv.w;
    s.x = zv.x + d.x;  s.y = zv.y + d.y;  s.z = zv.z + d.z;  s.w = zv.w + d.w;
    ((float4*)(out + (size_t)m * DDIM))[tid] = s;
    t.x = s.x - zv.x; t.y = s.y - zv.y; t.z = s.z - zv.z; t.w = s.w - zv.w;
    float ls = t.x * t.x + t.y * t.y + t.z * t.z + t.w * t.w;
    #pragma unroll
    for (int o = 16; o > 0; o >>= 1) ls += __shfl_down_sync(0xffffffffu, ls, o);
    __shared__ float ws[4];
    if ((tid & 31) == 0) ws[tid >> 5] = ls;
    __syncthreads();
    if (tid == 0) {
        g_tokloss[m] = ws[0] + ws[1] + ws[2] + ws[3];
        atomicAdd(&g_counts[c], 1);
        if (writeCodes) outCodes[m] = (float)c;
    }
}

__global__ void finalize_kernel(float* __restrict__ outStats, int M, int C, int hasStats) {
    __shared__ float sh[1024];
    int tid = threadIdx.x;
    float s = 0.f;
    for (int i = tid; i < M; i += 1024) s += g_tokloss[i];
    sh[tid] = s; __syncthreads();
    for (int o = 512; o > 0; o >>= 1) { if (tid < o) sh[tid] += sh[tid + o]; __syncthreads(); }
    float loss = 0.25f * sh[0] / ((float)M * (float)DDIM);
    __syncthreads();
    float p = 0.f;
    float invM = 1.f / (float)M;
    for (int i = tid; i < C; i += 1024) {
        float pr = (float)g_counts[i] * invM;
        p += pr * logf(pr + 1e-10f);
    }
    sh[tid] = p; __syncthreads();
    for (int o = 512; o > 0; o >>= 1) { if (tid < o) sh[tid] += sh[tid + o]; __syncthreads(); }
    if (tid == 0 && hasStats) {
        outStats[0] = loss;
        outStats[1] = expf(-sh[0]);
    }
}

extern "C" void kernel_launch(void* const* d_in, const int* in_sizes, int n_in,
                              void* d_out, int out_size) {
    const float* z   = (const float*)d_in[0];
    const float* emb = (const float*)d_in[1];
    float* out = (float*)d_out;

    int M = in_sizes[0] / DDIM;   // 32768
    int C = in_sizes[1] / DDIM;   // 8192

    static int attr_done = 0;
    if (!attr_done) {
        cudaFuncSetAttribute(hmma_argmin_kernel, cudaFuncAttributeMaxDynamicSharedMemorySize, DYN_SMEM);
        attr_done = 1;
    }

    char* zq; cudaGetSymbolAddress((void**)&zq, g_zq);
    char* eq; cudaGetSymbolAddress((void**)&eq, g_eq);

    init_kernel<<<(MTOK + 255) / 256, 256>>>();                       // 1
    convert_kernel<<<(M * DDIM / 4 + 255) / 256, 256>>>(z, zq, M * DDIM / 4);  // 2
    convert_enorm_kernel<<<C, 128>>>(emb, eq);                        // 3
    hmma_argmin_kernel<<<M / MT, CTA_THR, DYN_SMEM>>>(C);             // 4  <-- profiled slot
    filter_b_kernel<<<NTHREADS_TOT / 256, 256>>>();                   // 5
    exact_kernel<<<1024, 256>>>(z, emb);                              // 6
    fallback_kernel<<<256, 256>>>(z, emb);                            // 7
    long long zqN = (long long)M * DDIM;
    int writeCodes = (out_size >= zqN + M) ? 1 : 0;
    gather_kernel<<<M, 128>>>(z, emb, out, out + zqN, writeCodes);    // 8
    int hasStats = (out_size >= zqN + M + 2) ? 1 : 0;
    finalize_kernel<<<1, 1024>>>(out + zqN + M, M, C, hasStats);      // 9
}

// round 14
// speedup vs baseline: 2.5643x; 2.5562x over previous
#include <cuda_runtime.h>
#include <cuda_fp16.h>
#include <math.h>
#include <stdint.h>

#define DDIM   512
#define MTOK   32768
#define NCODE  8192
#define MT     128
#define NTILE  128
#define BK     64
#define NSTG   3
#define MARGIN 0.25f
#define CAP    160
#define NTHREADS_TOT 65536          // 256 CTAs x 256 threads
#define SURV_MAX (1 << 20)

#define A_BYTES (MT*BK*2)
#define B_BYTES (NTILE*BK*2)
#define STG_BYTES (A_BYTES + B_BYTES)
#define DYN_SMEM (NSTG * STG_BYTES)   // 96KB

#define SWZ(o) ((o) ^ ((((o) >> 3) & 0x70)))

// ---------------- device scratch ----------------
__device__ __half g_zh[(size_t)MTOK * DDIM];
__device__ __half g_eh[(size_t)NCODE * DDIM];
__device__ float g_enorm[NCODE];
__device__ int   g_counts[NCODE];
__device__ float g_tokloss[MTOK];
__device__ unsigned long long g_key[MTOK];
__device__ unsigned long long g_ent[(size_t)NTHREADS_TOT * CAP];
__device__ int   g_cnt[NTHREADS_TOT];
__device__ unsigned int  g_bestbits[MTOK];
__device__ unsigned char g_overflow[MTOK];
__device__ int   g_surv[SURV_MAX];
__device__ int   g_nsurv;

// ---------------- helpers ----------------
__device__ __forceinline__ uint32_t smem_u32(const void* p) {
    return (uint32_t)__cvta_generic_to_shared(p);
}
__device__ __forceinline__ void cpasync16(uint32_t dst, const void* src) {
    asm volatile("cp.async.cg.shared.global [%0], [%1], 16;" :: "r"(dst), "l"(src) : "memory");
}
__device__ __forceinline__ void cp_commit() {
    asm volatile("cp.async.commit_group;" ::: "memory");
}
template<int N> __device__ __forceinline__ void cp_wait() {
    asm volatile("cp.async.wait_group %0;" :: "n"(N) : "memory");
}
__device__ __forceinline__ void ldsm4(uint32_t& r0, uint32_t& r1, uint32_t& r2, uint32_t& r3,
                                      uint32_t a) {
    asm volatile("ldmatrix.sync.aligned.m8n8.x4.shared.b16 {%0,%1,%2,%3}, [%4];"
                 : "=r"(r0), "=r"(r1), "=r"(r2), "=r"(r3) : "r"(a));
}
__device__ __forceinline__ void mma16816(float* c, const uint32_t* a, const uint32_t* b) {
    asm volatile(
        "mma.sync.aligned.m16n8k16.row.col.f32.f16.f16.f32 "
        "{%0,%1,%2,%3}, {%4,%5,%6,%7}, {%8,%9}, {%0,%1,%2,%3};"
        : "+f"(c[0]), "+f"(c[1]), "+f"(c[2]), "+f"(c[3])
        : "r"(a[0]), "r"(a[1]), "r"(a[2]), "r"(a[3]), "r"(b[0]), "r"(b[1]));
}
__device__ __forceinline__ unsigned orderbits(float v) {
    unsigned u = __float_as_uint(v);
    return (u & 0x80000000u) ? ~u : (u | 0x80000000u);
}
__device__ __forceinline__ float unorderf(unsigned u) {
    u = (u & 0x80000000u) ? (u & 0x7FFFFFFFu) : ~u;
    return __uint_as_float(u);
}
__device__ __forceinline__ unsigned long long packkey(float d, int c) {
    return ((unsigned long long)orderbits(d) << 32) | (unsigned)c;
}

// ---------------- setup ----------------
__global__ void init_kernel() {
    int i = blockIdx.x * blockDim.x + threadIdx.x;
    if (i < NCODE) g_counts[i] = 0;
    if (i < MTOK) {
        g_key[i] = 0xFFFFFFFFFFFFFFFFull;
        g_bestbits[i] = 0xFFFFFFFFu;
        g_overflow[i] = 0;
    }
    if (i == 0) g_nsurv = 0;
}

__global__ void convert_kernel(const float* __restrict__ x, __half* __restrict__ out, int n4) {
    int i = blockIdx.x * blockDim.x + threadIdx.x;
    if (i >= n4) return;
    float4 v = ((const float4*)x)[i];
    ((__half2*)out)[i * 2]     = __floats2half2_rn(v.x, v.y);
    ((__half2*)out)[i * 2 + 1] = __floats2half2_rn(v.z, v.w);
}

__global__ void convert_enorm_kernel(const float* __restrict__ emb, __half* __restrict__ out) {
    int c = blockIdx.x, tid = threadIdx.x;
    const float4* src = (const float4*)(emb + (size_t)c * DDIM);
    float4 v = src[tid];
    ((__half2*)(out + (size_t)c * DDIM))[tid * 2]     = __floats2half2_rn(v.x, v.y);
    ((__half2*)(out + (size_t)c * DDIM))[tid * 2 + 1] = __floats2half2_rn(v.z, v.w);
    float s = v.x * v.x + v.y * v.y + v.z * v.z + v.w * v.w;
    #pragma unroll
    for (int o = 16; o > 0; o >>= 1) s += __shfl_down_sync(0xffffffffu, s, o);
    __shared__ float ws[4];
    if ((tid & 31) == 0) ws[tid >> 5] = s;
    __syncthreads();
    if (tid == 0) g_enorm[c] = ws[0] + ws[1] + ws[2] + ws[3];
}

// ---------------- fused HMMA GEMM + candidate emission + screen-best publish ----------------
__global__ void __launch_bounds__(256, 2) hmma_argmin_kernel(int C) {
    extern __shared__ __align__(1024) char dyn[];
    const uint32_t sb = smem_u32(dyn);
    const int tid = threadIdx.x;
    const int wid = tid >> 5, l = tid & 31;
    const int wm = wid >> 1, wn = wid & 1;
    const int m0 = blockIdx.x * MT;
    const int nct = C / NTILE;
    const int TOT = nct * 8;

    const __half* Z = g_zh;
    const __half* E = g_eh;

    float rbest[4];
    #pragma unroll
    for (int r = 0; r < 4; r++) rbest[r] = 3.0e38f;
    uint32_t mmeta[4];
    #pragma unroll
    for (int r = 0; r < 4; r++) {
        int am = r >> 1, h = r & 1;
        int row = wm * 32 + am * 16 + h * 8 + (l >> 2);
        mmeta[r] = (uint32_t)(m0 + row) << 13;
    }
    int cnt = 0;
    unsigned long long* ent = g_ent + (size_t)(blockIdx.x * 256 + tid) * CAP;

    auto load_chunk = [&](int i) {
        int t = i >> 3, ch = i & 7;
        int kk0 = ch * BK;
        int c0 = t * NTILE;
        uint32_t abase = sb + (i % NSTG) * STG_BYTES;
        uint32_t bbase = abase + A_BYTES;
        #pragma unroll
        for (int q = 0; q < 4; q++) {
            int f = tid + q * 256;
            int row = f >> 3, kq = (f & 7) * 8;
            cpasync16(abase + SWZ(row * 128 + kq * 2),
                      Z + ((size_t)(m0 + row) * DDIM + kk0 + kq));
            cpasync16(bbase + SWZ(row * 128 + kq * 2),
                      E + ((size_t)(c0 + row) * DDIM + kk0 + kq));
        }
        cp_commit();
    };

    load_chunk(0);
    load_chunk(1);

    float acc[2][8][4];
    #pragma unroll
    for (int am = 0; am < 2; am++)
        #pragma unroll
        for (int bn = 0; bn < 8; bn++)
            #pragma unroll
            for (int k = 0; k < 4; k++) acc[am][bn][k] = 0.f;

    const int arow = wm * 32 + (l & 7) + ((l >> 3) & 1) * 8;
    const int acol = (l >> 4) * 16;
    const uint32_t axor = (uint32_t)((arow & 7) << 4);
    const uint32_t aoff0 = (uint32_t)(arow * 128);
    const int brow = wn * 64 + (l & 7) + (l >> 4) * 8;
    const int bcol = ((l >> 3) & 1) * 16;
    const uint32_t bxor = (uint32_t)((brow & 7) << 4);
    const uint32_t boff0 = (uint32_t)(brow * 128);

    for (int i = 0; i < TOT; i++) {
        if (i + 1 < TOT) cp_wait<1>(); else cp_wait<0>();
        __syncthreads();
        if (i + 2 < TOT) load_chunk(i + 2);

        uint32_t abase = sb + (i % NSTG) * STG_BYTES;
        uint32_t bbase = abase + A_BYTES;

        #pragma unroll
        for (int kk = 0; kk < 4; kk++) {
            const uint32_t akb = ((uint32_t)(kk * 32 + acol)) ^ axor;
            const uint32_t bkb = ((uint32_t)(kk * 32 + bcol)) ^ bxor;
            uint32_t af[2][4];
            #pragma unroll
            for (int am = 0; am < 2; am++)
                ldsm4(af[am][0], af[am][1], af[am][2], af[am][3],
                      abase + aoff0 + (uint32_t)(am * 2048) + akb);
            uint32_t bcur[4], bnxt[4];
            ldsm4(bcur[0], bcur[1], bcur[2], bcur[3], bbase + boff0 + bkb);
            #pragma unroll
            for (int bp = 0; bp < 4; bp++) {
                if (bp < 3)
                    ldsm4(bnxt[0], bnxt[1], bnxt[2], bnxt[3],
                          bbase + boff0 + (uint32_t)((bp + 1) * 2048) + bkb);
                #pragma unroll
                for (int am = 0; am < 2; am++) {
                    mma16816(acc[am][2 * bp],     af[am], bcur);
                    mma16816(acc[am][2 * bp + 1], af[am], bcur + 2);
                }
                #pragma unroll
                for (int q = 0; q < 4; q++) bcur[q] = bnxt[q];
            }
        }

        if ((i & 7) == 7) {
            int c0 = (i >> 3) * NTILE;
            #pragma unroll
            for (int bn = 0; bn < 8; bn++) {
                #pragma unroll
                for (int j = 0; j < 2; j++) {
                    int c = c0 + wn * 64 + bn * 8 + (l & 3) * 2 + j;
                    float e = __ldg(&g_enorm[c]);
                    #pragma unroll
                    for (int am = 0; am < 2; am++) {
                        #pragma unroll
                        for (int h = 0; h < 2; h++) {
                            int r = am * 2 + h;
                            float v = fmaf(-2.f, acc[am][bn][h * 2 + j], e);
                            if (v < rbest[r] + MARGIN) {
                                int pos = cnt < CAP ? cnt : CAP - 1;
                                ent[pos] = ((unsigned long long)(mmeta[r] | (uint32_t)c) << 32)
                                         | __float_as_uint(v);
                                cnt++;
                            }
                            rbest[r] = fminf(rbest[r], v);
                        }
                    }
                }
            }
            #pragma unroll
            for (int am = 0; am < 2; am++)
                #pragma unroll
                for (int bn = 0; bn < 8; bn++)
                    #pragma unroll
                    for (int k = 0; k < 4; k++) acc[am][bn][k] = 0.f;
        }
    }

    g_cnt[blockIdx.x * 256 + tid] = cnt;
    // fused filter A: publish per-slot screen best + inline overflow marking
    #pragma unroll
    for (int r = 0; r < 4; r++) {
        int m = (int)(mmeta[r] >> 13);
        atomicMin(&g_bestbits[m], orderbits(rbest[r]));
        if (cnt > CAP) g_overflow[m] = 1;
    }
}

// ---------------- filter B: compact survivors vs global screen best ----------------
__global__ void filter_b_kernel() {
    int gid = blockIdx.x * blockDim.x + threadIdx.x;
    int cnt = g_cnt[gid];
    if (cnt > CAP) cnt = CAP;
    const unsigned long long* ent = g_ent + (size_t)gid * CAP;
    for (int i = 0; i < cnt; i++) {
        unsigned long long e = ent[i];
        unsigned meta = (unsigned)(e >> 32);
        float v = __uint_as_float((unsigned)e);
        int m = meta >> 13;
        float best = unorderf(g_bestbits[m]);
        if (v < best + MARGIN) {
            int pos = atomicAdd(&g_nsurv, 1);
            if (pos < SURV_MAX) g_surv[pos] = (int)meta;
            else g_overflow[m] = 1;
        }
    }
}

// ---------------- exact fp32 scoring of survivors ----------------
__global__ void __launch_bounds__(256) exact_kernel(const float* __restrict__ z,
                                                    const float* __restrict__ emb) {
    int n = g_nsurv;
    if (n > SURV_MAX) n = SURV_MAX;
    int gw = blockIdx.x * 8 + (threadIdx.x >> 5);
    int l = threadIdx.x & 31;
    const int NW = gridDim.x * 8;
    for (int i = gw; i < n; i += NW) {
        unsigned meta = (unsigned)g_surv[i];
        int m = meta >> 13, c = meta & 0x1FFF;
        const float4* zr = (const float4*)(z + (size_t)m * DDIM);
        const float4* er = (const float4*)(emb + (size_t)c * DDIM);
        float a0 = 0.f, a1 = 0.f;
        #pragma unroll
        for (int q = 0; q < 4; q++) {
            float4 zv = __ldg(zr + q * 32 + l);
            float4 ev = __ldg(er + q * 32 + l);
            a0 = fmaf(zv.x, ev.x, a0);
            a1 = fmaf(zv.y, ev.y, a1);
            a0 = fmaf(zv.z, ev.z, a0);
            a1 = fmaf(zv.w, ev.w, a1);
        }
        float s = a0 + a1;
        #pragma unroll
        for (int o = 16; o > 0; o >>= 1) s += __shfl_down_sync(0xffffffffu, s, o);
        if (l == 0) {
            float v = fmaf(-2.f, s, __ldg(&g_enorm[c]));
            atomicMin(&g_key[m], packkey(v, c));
        }
    }
}

// ---------------- fallback: full exact scan for overflowed tokens (expected none) ----------------
__global__ void __launch_bounds__(256) fallback_kernel(const float* __restrict__ z,
                                                       const float* __restrict__ emb) {
    for (int m = blockIdx.x; m < MTOK; m += gridDim.x) {
        if (!g_overflow[m]) continue;
        int tid = threadIdx.x;
        for (int c = tid; c < NCODE; c += 256) {
            const float* zr = z + (size_t)m * DDIM;
            const float* er = emb + (size_t)c * DDIM;
            float a = 0.f;
            for (int k = 0; k < DDIM; k++) a = fmaf(__ldg(zr + k), __ldg(er + k), a);
            float v = fmaf(-2.f, a, __ldg(&g_enorm[c]));
            atomicMin(&g_key[m], packkey(v, c));
        }
    }
}

// ---------------- gather / stats ----------------
__global__ void gather_kernel(const float* __restrict__ z, const float* __restrict__ emb,
                              float* __restrict__ out, float* __restrict__ outCodes,
                              int writeCodes) {
    int m = blockIdx.x, tid = threadIdx.x;
    int c = (int)(g_key[m] & 0x1FFFull);
    float4 zv = ((const float4*)(z + (size_t)m * DDIM))[tid];
    float4 ev = ((const float4*)(emb + (size_t)c * DDIM))[tid];
    float4 d, s, t;
    d.x = ev.x - zv.x; d.y = ev.y - zv.y; d.z = ev.z - zv.z; d.w = ev.w - zv.w;
    s.x = zv.x + d.x;  s.y = zv.y + d.y;  s.z = zv.z + d.z;  s.w = zv.w + d.w;
    ((float4*)(out + (size_t)m * DDIM))[tid] = s;
    t.x = s.x - zv.x; t.y = s.y - zv.y; t.z = s.z - zv.z; t.w = s.w - zv.w;
    float ls = t.x * t.x + t.y * t.y + t.z * t.z + t.w * t.w;
    #pragma unroll
    for (int o = 16; o > 0; o >>= 1) ls += __shfl_down_sync(0xffffffffu, ls, o);
    __shared__ float ws[4];
    if ((tid & 31) == 0) ws[tid >> 5] = ls;
    __syncthreads();
    if (tid == 0) {
        g_tokloss[m] = ws[0] + ws[1] + ws[2] + ws[3];
        atomicAdd(&g_counts[c], 1);
        if (writeCodes) outCodes[m] = (float)c;
    }
}

__global__ void finalize_kernel(float* __restrict__ outStats, int M, int C, int hasStats) {
    __shared__ float sh[1024];
    int tid = threadIdx.x;
    float s = 0.f;
    for (int i = tid; i < M; i += 1024) s += g_tokloss[i];
    sh[tid] = s; __syncthreads();
    for (int o = 512; o > 0; o >>= 1) { if (tid < o) sh[tid] += sh[tid + o]; __syncthreads(); }
    float loss = 0.25f * sh[0] / ((float)M * (float)DDIM);
    __syncthreads();
    float p = 0.f;
    float invM = 1.f / (float)M;
    for (int i = tid; i < C; i += 1024) {
        float pr = (float)g_counts[i] * invM;
        p += pr * logf(pr + 1e-10f);
    }
    sh[tid] = p; __syncthreads();
    for (int o = 512; o > 0; o >>= 1) { if (tid < o) sh[tid] += sh[tid + o]; __syncthreads(); }
    if (tid == 0 && hasStats) {
        outStats[0] = loss;
        outStats[1] = expf(-sh[0]);
    }
}

extern "C" void kernel_launch(void* const* d_in, const int* in_sizes, int n_in,
                              void* d_out, int out_size) {
    const float* z   = (const float*)d_in[0];
    const float* emb = (const float*)d_in[1];
    float* out = (float*)d_out;

    int M = in_sizes[0] / DDIM;   // 32768
    int C = in_sizes[1] / DDIM;   // 8192

    static int attr_done = 0;
    if (!attr_done) {
        cudaFuncSetAttribute(hmma_argmin_kernel, cudaFuncAttributeMaxDynamicSharedMemorySize, DYN_SMEM);
        attr_done = 1;
    }

    __half* zh; cudaGetSymbolAddress((void**)&zh, g_zh);
    __half* eh; cudaGetSymbolAddress((void**)&eh, g_eh);

    init_kernel<<<(MTOK + 255) / 256, 256>>>();                       // 1
    convert_kernel<<<(M * DDIM / 4 + 255) / 256, 256>>>(z, zh, M * DDIM / 4);  // 2
    convert_enorm_kernel<<<C, 128>>>(emb, eh);                        // 3
    hmma_argmin_kernel<<<M / MT, 256, DYN_SMEM>>>(C);                 // 4  <-- profiled slot
    filter_b_kernel<<<NTHREADS_TOT / 256, 256>>>();                   // 5
    exact_kernel<<<1024, 256>>>(z, emb);                              // 6
    fallback_kernel<<<256, 256>>>(z, emb);                            // 7
    long long zqN = (long long)M * DDIM;
    int writeCodes = (out_size >= zqN + M) ? 1 : 0;
    gather_kernel<<<M, 128>>>(z, emb, out, out + zqN, writeCodes);    // 8
    int hasStats = (out_size >= zqN + M + 2) ? 1 : 0;
    finalize_kernel<<<1, 1024>>>(out + zqN + M, M, C, hasStats);      // 9
}